// round 16
// baseline (speedup 1.0000x reference)
#include <cuda_runtime.h>
#include <cuda_fp16.h>
#include <cstdint>

#define Hd   2048
#define NHd  16
#define DHd  128
#define Bd   4
#define Sd   2048
#define Ad   512

// ---------------- scratch (static device arrays; no allocation) ----------------
__device__ __half g_hidh[(size_t)Bd * Sd * Hd];
__device__ __half g_audh[(size_t)Bd * Ad * Hd];
__device__ __half g_Wh[4][(size_t)Hd * Hd];       // fp16 weights, natural [k][n]
__device__ __half g_Qh[(size_t)Bd * Sd * Hd];
__device__ __half g_Kh[(size_t)Bd * Ad * Hd];
__device__ __half g_Vh[(size_t)Bd * Ad * Hd];
__device__ __half g_ctxh[(size_t)Bd * Sd * Hd];
__device__ float  g_att[(size_t)Bd * Sd * Hd];    // out_proj + residual (fp32)

// ---------------- helpers ----------------
__device__ __forceinline__ void cp16(void* dst, const void* src) {
    uint32_t d = (uint32_t)__cvta_generic_to_shared(dst);
    asm volatile("cp.async.cg.shared.global [%0], [%1], 16;\n" :: "r"(d), "l"(src));
}
#define CP_COMMIT asm volatile("cp.async.commit_group;\n" ::: "memory")
#define CP_WAIT0  asm volatile("cp.async.wait_group 0;\n" ::: "memory")
#define CP_WAIT1  asm volatile("cp.async.wait_group 1;\n" ::: "memory")
#define CP_WAIT2  asm volatile("cp.async.wait_group 2;\n" ::: "memory")

__device__ __forceinline__ uint32_t smaddr(const void* p) {
    return (uint32_t)__cvta_generic_to_shared(p);
}

__device__ __forceinline__ void ldm4(uint32_t r[4], uint32_t a) {
    asm volatile("ldmatrix.sync.aligned.m8n8.x4.shared.b16 {%0,%1,%2,%3}, [%4];"
                 : "=r"(r[0]), "=r"(r[1]), "=r"(r[2]), "=r"(r[3]) : "r"(a));
}
__device__ __forceinline__ void ldm4t(uint32_t r[4], uint32_t a) {
    asm volatile("ldmatrix.sync.aligned.m8n8.x4.trans.shared.b16 {%0,%1,%2,%3}, [%4];"
                 : "=r"(r[0]), "=r"(r[1]), "=r"(r[2]), "=r"(r[3]) : "r"(a));
}

__device__ __forceinline__ void mma_f16(float c[4], const uint32_t a[4], const uint32_t b[2]) {
    asm volatile(
        "mma.sync.aligned.m16n8k16.row.col.f32.f16.f16.f32 "
        "{%0,%1,%2,%3}, {%4,%5,%6,%7}, {%8,%9}, {%0,%1,%2,%3};"
        : "+f"(c[0]), "+f"(c[1]), "+f"(c[2]), "+f"(c[3])
        : "r"(a[0]), "r"(a[1]), "r"(a[2]), "r"(a[3]), "r"(b[0]), "r"(b[1]));
}

__device__ __forceinline__ uint32_t packf2(float a, float b) {
    __half2 h = __floats2half2_rn(a, b);
    return *(uint32_t*)&h;
}

// =====================================================================
// One-shot convert: hidden, audio, 4 weights -> fp16 (range-selected)
// =====================================================================
__global__ void __launch_bounds__(256) convert_all_kernel(
    const float* __restrict__ hid, const float* __restrict__ aud,
    const float* __restrict__ w0, const float* __restrict__ w1,
    const float* __restrict__ w2, const float* __restrict__ w3)
{
    int b = blockIdx.x;
    const float* src;
    __half* dst;
    int off;
    if (b < 16384)      { src = hid; dst = g_hidh; off = b; }
    else if (b < 20480) { src = aud; dst = g_audh; off = b - 16384; }
    else {
        int t  = b - 20480;
        int wi = t >> 12;
        off    = t & 4095;
        src = (wi == 0) ? w0 : (wi == 1) ? w1 : (wi == 2) ? w2 : w3;
        dst = g_Wh[wi];
    }
    int i = off * 256 + threadIdx.x;
    float4 v = ((const float4*)src)[i];
    __half2* o2 = (__half2*)dst;
    o2[2 * i]     = __floats2half2_rn(v.x, v.y);
    o2[2 * i + 1] = __floats2half2_rn(v.z, v.w);
}

// =====================================================================
// fp16 GEMM body with intra-chunk fragment pipelining:
//   all 12 ldmatrix for both kk-steps issued up front, then 32 MMAs.
//   BK=32, 256 threads (8 warps 2x4, warp tile 64x32), 3-stage cp.async.
// =====================================================================
#define GEMM_SMEM_BYTES (3 * 128 * 40 * 2 + 3 * 32 * 136 * 2)   // 56832

template<bool HALF_OUT, bool RES>
__device__ __forceinline__ void gemm_body(
    char* gsm,
    const __half* __restrict__ X, const __half* __restrict__ W,
    const float* __restrict__ bias, const float* __restrict__ res,
    void* __restrict__ Cout, int m0, int n0)
{
    __half (*As)[128][40] = (__half (*)[128][40])gsm;             // [3][128][40]
    __half (*Bs)[32][136] = (__half (*)[32][136])(gsm + 30720);   // [3][32][136]

    const int tid  = threadIdx.x;
    const int lane = tid & 31, wid = tid >> 5;
    const int g    = lane >> 2, tig = lane & 3;
    const int wm   = wid >> 2,  wn  = wid & 3;

    const int ar = tid >> 1;
    const int ac = (tid & 1) * 16;
    const int brow = tid >> 3;
    const int bcol = (tid & 7) * 8;

    const int lm_r = (lane & 7) + ((lane >> 3) & 1) * 8;   // A (non-trans)
    const int lm_c = (lane >> 4) * 8;
    const int vt_r = (lane & 7) + ((lane >> 3) & 1) * 8;   // B (trans): rows = k
    const int vt_c = (lane >> 4) * 8;

    float acc[4][4][4];
    #pragma unroll
    for (int mi = 0; mi < 4; mi++)
        #pragma unroll
        for (int ni = 0; ni < 4; ni++)
            #pragma unroll
            for (int j = 0; j < 4; j++) acc[mi][ni][j] = 0.0f;

    auto load_stage = [&](int st, int k0) {
        const __half* xs = X + (size_t)(m0 + ar) * Hd + k0 + ac;
        cp16(&As[st][ar][ac],     xs);
        cp16(&As[st][ar][ac + 8], xs + 8);
        const __half* ws = W + (size_t)(k0 + brow) * Hd + n0 + bcol;
        cp16(&Bs[st][brow][bcol],      ws);
        cp16(&Bs[st][brow][bcol + 64], ws + 64);
        CP_COMMIT;
    };

    load_stage(0, 0);
    load_stage(1, 32);

    #pragma unroll 1
    for (int c = 0; c < Hd / 32; c++) {
        const int st = c % 3;
        CP_WAIT1;
        __syncthreads();
        if (c + 2 < Hd / 32) load_stage((c + 2) % 3, (c + 2) * 32);

        // ---- issue ALL fragment loads for both kk-steps first ----
        uint32_t af[2][4][4];
        uint32_t bf[2][4][2];
        #pragma unroll
        for (int hh = 0; hh < 2; hh++) {
            const int kk = hh * 16;
            #pragma unroll
            for (int mi = 0; mi < 4; mi++)
                ldm4(af[hh][mi], smaddr(&As[st][wm * 64 + mi * 16 + lm_r][kk + lm_c]));
            #pragma unroll
            for (int nb = 0; nb < 2; nb++) {
                uint32_t t4[4];
                ldm4t(t4, smaddr(&Bs[st][kk + vt_r][wn * 32 + nb * 16 + vt_c]));
                bf[hh][2 * nb][0]     = t4[0];
                bf[hh][2 * nb][1]     = t4[1];
                bf[hh][2 * nb + 1][0] = t4[2];
                bf[hh][2 * nb + 1][1] = t4[3];
            }
        }
        // ---- then all 32 MMAs (same accumulation order as before) ----
        #pragma unroll
        for (int hh = 0; hh < 2; hh++)
            #pragma unroll
            for (int mi = 0; mi < 4; mi++)
                #pragma unroll
                for (int ni = 0; ni < 4; ni++)
                    mma_f16(acc[mi][ni], af[hh][mi], bf[hh][ni]);
    }

    #pragma unroll
    for (int mi = 0; mi < 4; mi++) {
        #pragma unroll
        for (int ni = 0; ni < 4; ni++) {
            int r = m0 + wm * 64 + mi * 16 + g;
            int c = n0 + wn * 32 + ni * 8 + tig * 2;
            float v0 = acc[mi][ni][0] + bias[c];
            float v1 = acc[mi][ni][1] + bias[c + 1];
            float v2 = acc[mi][ni][2] + bias[c];
            float v3 = acc[mi][ni][3] + bias[c + 1];
            if (RES) {
                float2 r0 = *(const float2*)(res + (size_t)r * Hd + c);
                float2 r1 = *(const float2*)(res + (size_t)(r + 8) * Hd + c);
                v0 += r0.x; v1 += r0.y; v2 += r1.x; v3 += r1.y;
            }
            if (HALF_OUT) {
                __half* C = (__half*)Cout;
                *(__half2*)(C + (size_t)r * Hd + c)       = __floats2half2_rn(v0, v1);
                *(__half2*)(C + (size_t)(r + 8) * Hd + c) = __floats2half2_rn(v2, v3);
            } else {
                float* C = (float*)Cout;
                *(float2*)(C + (size_t)r * Hd + c)       = make_float2(v0, v1);
                *(float2*)(C + (size_t)(r + 8) * Hd + c) = make_float2(v2, v3);
            }
        }
    }
}

// =====================================================================
// Merged Q/K/V projection launch: 1536 CTAs
// =====================================================================
__global__ void __launch_bounds__(256, 2) qkv_kernel(
    const float* __restrict__ bq, const float* __restrict__ bk,
    const float* __restrict__ bv)
{
    extern __shared__ char gsm[];
    const int bid = blockIdx.x;
    const __half* X;
    const __half* W;
    const float* bias;
    __half* out;
    int m0, n0;
    if (bid < 1024) {
        X = g_hidh; W = g_Wh[0]; bias = bq; out = g_Qh;
        m0 = (bid >> 4) * 128; n0 = (bid & 15) * 128;
    } else if (bid < 1280) {
        int t = bid - 1024;
        X = g_audh; W = g_Wh[1]; bias = bk; out = g_Kh;
        m0 = (t >> 4) * 128; n0 = (t & 15) * 128;
    } else {
        int t = bid - 1280;
        X = g_audh; W = g_Wh[2]; bias = bv; out = g_Vh;
        m0 = (t >> 4) * 128; n0 = (t & 15) * 128;
    }
    gemm_body<true, false>(gsm, X, W, bias, nullptr, out, m0, n0);
}

// =====================================================================
// Output projection + residual: fp32 out
// =====================================================================
__global__ void __launch_bounds__(256, 2) wo_kernel(
    const float* __restrict__ bo, const float* __restrict__ hidden)
{
    extern __shared__ char gsm[];
    gemm_body<false, true>(gsm, g_ctxh, g_Wh[3], bo, hidden, g_att,
                           (int)(blockIdx.y * 128), (int)(blockIdx.x * 128));
}

// =====================================================================
// Flash attention (unchanged): CTA = 64 q-rows x one head, 128 threads.
// smem: K[2] + V[2] (4 x 17408) + mv 512f = 71,680 B -> 3 CTAs/SM
// =====================================================================
#define AT_K   0
#define AT_V   34816
#define AT_MV  69632
#define ATTN_SMEM_BYTES 71680

__global__ void __launch_bounds__(128) attn_kernel(const float* __restrict__ mask)
{
    extern __shared__ char smc[];
    float* mv = (float*)(smc + AT_MV);

    const int tid  = threadIdx.x;
    const int lane = tid & 31, wid = tid >> 5;
    const int g    = lane >> 2, tig = lane & 3;

    const int bx = blockIdx.x;
    const int qt = bx & 31;
    const int h  = (bx >> 5) & 15;
    const int b  = bx >> 9;
    const int qrow0 = b * Sd + qt * 64;
    const int krow0 = b * Ad;
    const int hoff  = h * DHd;
    const float scale = 0.0883883476483184f;

    auto load_tile = [&](char* dstbase, const __half* src_base) {
        __half (*dst)[136] = (__half (*)[136])dstbase;
        #pragma unroll
        for (int p = 0; p < 8; p++) {
            int i = tid + p * 128;
            int r = i >> 4, c = (i & 15) * 8;
            cp16(&dst[r][c], src_base + (size_t)r * Hd + c);
        }
        CP_COMMIT;
    };
    auto Kst = [&](int st) { return smc + AT_K + st * 17408; };
    auto Vst = [&](int st) { return smc + AT_V + st * 17408; };

    load_tile(Kst(0), g_Kh + (size_t)krow0 * Hd + hoff);
    load_tile(Vst(0), g_Vh + (size_t)krow0 * Hd + hoff);
    load_tile(Kst(1), g_Kh + (size_t)(krow0 + 64) * Hd + hoff);
    load_tile(Vst(1), g_Vh + (size_t)(krow0 + 64) * Hd + hoff);
    #pragma unroll
    for (int p = 0; p < 4; p++) {
        int i = tid + p * 128;
        mv[i] = mask[b * Ad + i] * -10000.0f;
    }

    uint32_t qf[8][4];
    {
        const __half* q0 = g_Qh + (size_t)(qrow0 + wid * 16 + g) * Hd + hoff;
        const __half* q1 = q0 + 8 * Hd;
        #pragma unroll
        for (int kk = 0; kk < 8; kk++) {
            qf[kk][0] = *(const uint32_t*)(q0 + kk * 16 + 2 * tig);
            qf[kk][1] = *(const uint32_t*)(q1 + kk * 16 + 2 * tig);
            qf[kk][2] = *(const uint32_t*)(q0 + kk * 16 + 2 * tig + 8);
            qf[kk][3] = *(const uint32_t*)(q1 + kk * 16 + 2 * tig + 8);
        }
    }

    float oacc[16][4];
    #pragma unroll
    for (int ni = 0; ni < 16; ni++)
        #pragma unroll
        for (int j = 0; j < 4; j++) oacc[ni][j] = 0.0f;
    float m0 = -1e30f, m1 = -1e30f, l0 = 0.0f, l1 = 0.0f;

    const int kq_r = (lane & 7) + (lane >> 4) * 8;
    const int kq_c = ((lane >> 3) & 1) * 8;
    const int vt_r = (lane & 7) + ((lane >> 3) & 1) * 8;
    const int vt_c = (lane >> 4) * 8;

    #pragma unroll 1
    for (int c = 0; c < 8; c++) {
        const int st = c & 1;
        if (c < 6) { CP_WAIT2; } else { CP_WAIT0; }
        __syncthreads();
        const __half (*Kb)[136] = (const __half (*)[136])Kst(st);
        const __half (*Vb)[136] = (const __half (*)[136])Vst(st);

        float sacc[8][4];
        #pragma unroll
        for (int ni = 0; ni < 8; ni++)
            #pragma unroll
            for (int j = 0; j < 4; j++) sacc[ni][j] = 0.0f;

        #pragma unroll
        for (int kk = 0; kk < 8; kk++) {
            uint32_t bf[8][2];
            #pragma unroll
            for (int nb = 0; nb < 4; nb++) {
                uint32_t t4[4];
                ldm4(t4, smaddr(&Kb[nb * 16 + kq_r][kk * 16 + kq_c]));
                bf[2 * nb][0]     = t4[0];
                bf[2 * nb][1]     = t4[1];
                bf[2 * nb + 1][0] = t4[2];
                bf[2 * nb + 1][1] = t4[3];
            }
            #pragma unroll
            for (int ni = 0; ni < 8; ni++)
                mma_f16(sacc[ni], qf[kk], bf[ni]);
        }

        const int cb = c * 64;
        float p[8][4];
        float rmax0 = -1e30f, rmax1 = -1e30f;
        #pragma unroll
        for (int ni = 0; ni < 8; ni++) {
            float mva = mv[cb + ni * 8 + 2 * tig];
            float mvb = mv[cb + ni * 8 + 2 * tig + 1];
            p[ni][0] = sacc[ni][0] * scale + mva;
            p[ni][1] = sacc[ni][1] * scale + mvb;
            p[ni][2] = sacc[ni][2] * scale + mva;
            p[ni][3] = sacc[ni][3] * scale + mvb;
            rmax0 = fmaxf(rmax0, fmaxf(p[ni][0], p[ni][1]));
            rmax1 = fmaxf(rmax1, fmaxf(p[ni][2], p[ni][3]));
        }
        rmax0 = fmaxf(rmax0, __shfl_xor_sync(0xffffffffu, rmax0, 1));
        rmax0 = fmaxf(rmax0, __shfl_xor_sync(0xffffffffu, rmax0, 2));
        rmax1 = fmaxf(rmax1, __shfl_xor_sync(0xffffffffu, rmax1, 1));
        rmax1 = fmaxf(rmax1, __shfl_xor_sync(0xffffffffu, rmax1, 2));
        float m0n = fmaxf(m0, rmax0), m1n = fmaxf(m1, rmax1);
        float cr0 = __expf(m0 - m0n), cr1 = __expf(m1 - m1n);
        float rs0 = 0.0f, rs1 = 0.0f;
        #pragma unroll
        for (int ni = 0; ni < 8; ni++) {
            p[ni][0] = __expf(p[ni][0] - m0n);
            p[ni][1] = __expf(p[ni][1] - m0n);
            p[ni][2] = __expf(p[ni][2] - m1n);
            p[ni][3] = __expf(p[ni][3] - m1n);
            rs0 += p[ni][0] + p[ni][1];
            rs1 += p[ni][2] + p[ni][3];
        }
        rs0 += __shfl_xor_sync(0xffffffffu, rs0, 1);
        rs0 += __shfl_xor_sync(0xffffffffu, rs0, 2);
        rs1 += __shfl_xor_sync(0xffffffffu, rs1, 1);
        rs1 += __shfl_xor_sync(0xffffffffu, rs1, 2);
        l0 = l0 * cr0 + rs0;  m0 = m0n;
        l1 = l1 * cr1 + rs1;  m1 = m1n;
        #pragma unroll
        for (int ni = 0; ni < 16; ni++) {
            oacc[ni][0] *= cr0; oacc[ni][1] *= cr0;
            oacc[ni][2] *= cr1; oacc[ni][3] *= cr1;
        }
        uint32_t pf[4][4];
        #pragma unroll
        for (int t = 0; t < 4; t++) {
            pf[t][0] = packf2(p[2 * t][0],     p[2 * t][1]);
            pf[t][1] = packf2(p[2 * t][2],     p[2 * t][3]);
            pf[t][2] = packf2(p[2 * t + 1][0], p[2 * t + 1][1]);
            pf[t][3] = packf2(p[2 * t + 1][2], p[2 * t + 1][3]);
        }

        #pragma unroll
        for (int t = 0; t < 4; t++) {
            #pragma unroll
            for (int nb = 0; nb < 8; nb++) {
                uint32_t t4[4];
                ldm4t(t4, smaddr(&Vb[t * 16 + vt_r][nb * 16 + vt_c]));
                mma_f16(oacc[2 * nb],     pf[t], t4);
                mma_f16(oacc[2 * nb + 1], pf[t], t4 + 2);
            }
        }

        __syncthreads();
        if (c + 2 < 8) {
            load_tile(Kst(st), g_Kh + (size_t)(krow0 + (c + 2) * 64) * Hd + hoff);
            load_tile(Vst(st), g_Vh + (size_t)(krow0 + (c + 2) * 64) * Hd + hoff);
        }
    }

    float i0 = 1.0f / l0, i1 = 1.0f / l1;
    const int row = qrow0 + wid * 16 + g;
    #pragma unroll
    for (int ni = 0; ni < 16; ni++) {
        int col = hoff + ni * 8 + 2 * tig;
        *(__half2*)(g_ctxh + (size_t)row * Hd + col) =
            __floats2half2_rn(oacc[ni][0] * i0, oacc[ni][1] * i0);
        *(__half2*)(g_ctxh + (size_t)(row + 8) * Hd + col) =
            __floats2half2_rn(oacc[ni][2] * i1, oacc[ni][3] * i1);
    }
}

// =====================================================================
// LayerNorm (input already includes residual)
// =====================================================================
__global__ void __launch_bounds__(256) ln_kernel(
    const float* __restrict__ gamma, const float* __restrict__ beta,
    float* __restrict__ out)
{
    const int row = blockIdx.x, t = threadIdx.x;
    const float4* a4 = (const float4*)(g_att + (size_t)row * Hd);

    float4 xv[2];
    float s = 0.0f, ss = 0.0f;
    #pragma unroll
    for (int p = 0; p < 2; p++) {
        int i = t + p * 256;
        float4 x = a4[i];
        xv[p] = x;
        s  += x.x + x.y + x.z + x.w;
        ss += x.x * x.x + x.y * x.y + x.z * x.z + x.w * x.w;
    }
    __shared__ float rs[8], rss[8];
    #pragma unroll
    for (int o = 16; o > 0; o >>= 1) {
        s  += __shfl_xor_sync(0xffffffffu, s, o);
        ss += __shfl_xor_sync(0xffffffffu, ss, o);
    }
    if ((t & 31) == 0) { rs[t >> 5] = s; rss[t >> 5] = ss; }
    __syncthreads();
    float ts = 0.0f, tss = 0.0f;
    #pragma unroll
    for (int i = 0; i < 8; i++) { ts += rs[i]; tss += rss[i]; }
    const float mean = ts * (1.0f / Hd);
    const float var  = tss * (1.0f / Hd) - mean * mean;
    const float inv  = rsqrtf(var + 1e-5f);

    const float4* g4 = (const float4*)gamma;
    const float4* b4 = (const float4*)beta;
    float4* o4 = (float4*)(out + (size_t)row * Hd);
    #pragma unroll
    for (int p = 0; p < 2; p++) {
        int i = t + p * 256;
        float4 gv = g4[i], bv = b4[i], x = xv[p];
        o4[i] = make_float4((x.x - mean) * inv * gv.x + bv.x,
                            (x.y - mean) * inv * gv.y + bv.y,
                            (x.z - mean) * inv * gv.z + bv.z,
                            (x.w - mean) * inv * gv.w + bv.w);
    }
}

// =====================================================================
// launcher: 5 kernels total
// =====================================================================
extern "C" void kernel_launch(void* const* d_in, const int* in_sizes, int n_in,
                              void* d_out, int out_size)
{
    const float* hidden = (const float*)d_in[0];
    const float* audio  = (const float*)d_in[1];
    const float* amask  = (const float*)d_in[2];
    const float* Wq = (const float*)d_in[3];
    const float* bq = (const float*)d_in[4];
    const float* Wk = (const float*)d_in[5];
    const float* bk = (const float*)d_in[6];
    const float* Wv = (const float*)d_in[7];
    const float* bv = (const float*)d_in[8];
    const float* Wo = (const float*)d_in[9];
    const float* bo = (const float*)d_in[10];
    const float* gamma = (const float*)d_in[11];
    const float* beta  = (const float*)d_in[12];
    float* out = (float*)d_out;

    cudaFuncSetAttribute(attn_kernel, cudaFuncAttributeMaxDynamicSharedMemorySize,
                         ATTN_SMEM_BYTES);
    cudaFuncSetAttribute(qkv_kernel, cudaFuncAttributeMaxDynamicSharedMemorySize,
                         GEMM_SMEM_BYTES);
    cudaFuncSetAttribute(wo_kernel, cudaFuncAttributeMaxDynamicSharedMemorySize,
                         GEMM_SMEM_BYTES);

    convert_all_kernel<<<36864, 256>>>(hidden, audio, Wq, Wk, Wv, Wo);
    qkv_kernel<<<1536, 256, GEMM_SMEM_BYTES>>>(bq, bk, bv);
    attn_kernel<<<Bd * NHd * (Sd / 64), 128, ATTN_SMEM_BYTES>>>(amask);
    wo_kernel<<<dim3(16, (Bd * Sd) / 128), 256, GEMM_SMEM_BYTES>>>(bo, hidden);
    ln_kernel<<<Bd * Sd, 256>>>(gamma, beta, out);
}